// round 11
// baseline (speedup 1.0000x reference)
#include <cuda_runtime.h>
#include <math.h>

// ---------- problem constants ----------
#define RECON_ELEMS 4194304 // 64*256*256
#define FORECAST_OFF RECON_ELEMS
#define ALPHA_OFF   (RECON_ELEMS + 16384)
#define RNN_BLOCKS  64

// ---------- scratch (static __device__, no allocations) ----------
__device__ float g_u[2097152];     // RNN input-proj U [32,256,256]
__device__ float g_y[2097152];     // RNN outputs [32,256,256] == nodes [8192,256]
__device__ float g_xl[4194304];    // [8192,512]
__device__ float g_xr[4194304];    // [8192,512]
__device__ float g_gat[4194304];   // [8192,512] == Z [16384,256]
__device__ float g_q[4194304];     // [16384,256]
__device__ float g_k[4194304];
__device__ float g_v[4194304];
__device__ float g_attn[4194304];  // [16384,256]
__device__ float g_fpart[65536];   // forecast partials [16384 elems][4 tiles]
__device__ int   g_offs[257];
__device__ int   g_elist[4096];
__device__ int   g_bar;            // grid barrier arrival count (0 between replays)
__device__ int   g_gen;            // grid barrier generation (monotonic)

// ---------- CSR build (deterministic, stable order) ----------
__global__ __launch_bounds__(256) void build_csr(const int* __restrict__ eidx,
                                                 int* __restrict__ offs,
                                                 int* __restrict__ elist)
{
    __shared__ int dsts[4096];
    __shared__ int cnt[256];
    __shared__ int off_s[257];
    int t = threadIdx.x;
    const int* dst = eidx + 4096;   // edge_idx[0][1][:]
    for (int j = t; j < 4096; j += 256) dsts[j] = dst[j];
    cnt[t] = 0;
    __syncthreads();
    for (int j = t; j < 4096; j += 256) atomicAdd(&cnt[dsts[j]], 1);
    __syncthreads();
    if (t == 0) {
        int run = 0;
        for (int i = 0; i < 256; i++) { off_s[i] = run; run += cnt[i]; }
        off_s[256] = run;
    }
    __syncthreads();
    offs[t] = off_s[t];
    if (t == 0) offs[256] = off_s[256];
    // stable fill: thread t owns destination value t; scans edges in j order
    int pos = off_s[t];
    for (int j = 0; j < 4096; j++) {
        if (dsts[j] == t) elist[pos++] = j;
    }
}

// ---------- persistent RNN scan: 32 steps, software grid barrier ----------
// H_b = tanh( U_b + H_{b-1} @ Whh^T + bhh ); 64 blocks (all co-resident),
// Whh tile cached in smem across all steps; A tile staged per step.
__device__ __forceinline__ void grid_barrier_64()
{
    __syncthreads();
    if (threadIdx.x == 0) {
        volatile int* vgen = &g_gen;
        int my_gen = *vgen;
        __threadfence();                       // publish this block's H writes
        int ticket = atomicAdd(&g_bar, 1);
        if (ticket == RNN_BLOCKS - 1) {
            g_bar = 0;                         // reset before release
            __threadfence();
            atomicAdd(&g_gen, 1);              // release
        } else {
            while (*vgen == my_gen) { }
        }
        __threadfence();                       // acquire
    }
    __syncthreads();
}

__global__ __launch_bounds__(256) void rnn_scan(
    const float* __restrict__ U,      // [32,256,256]
    const float* __restrict__ Whh,    // [256,256]
    const float* __restrict__ bhh,    // [256]
    float* __restrict__ Y)            // [32,256,256]
{
    extern __shared__ float sm[];
    float* sA = sm;                   // [256][34]
    float* sB = sm + 256 * 34;        // [256][34]
    int tid = threadIdx.x;
    int tx = tid & 15, ty = tid >> 4;
    int rowBase = (blockIdx.x >> 3) * 32;
    int colBase = (blockIdx.x & 7) * 32;

    // cache Whh tile once: sB[k][n] = Whh[(colBase+n)*256 + k]
    #pragma unroll 4
    for (int n = 0; n < 32; n++)
        sB[tid * 34 + n] = Whh[(size_t)(colBase + n) * 256 + tid];

    float bh0 = bhh[colBase + tx * 2];
    float bh1 = bhh[colBase + tx * 2 + 1];
    __syncthreads();

    // step 0: H0 = tanh(U0 + bhh)
    #pragma unroll
    for (int i = 0; i < 2; i++) {
        int row = rowBase + ty * 2 + i;
        int c0 = colBase + tx * 2;
        Y[row * 256 + c0]     = tanhf(U[row * 256 + c0]     + bh0);
        Y[row * 256 + c0 + 1] = tanhf(U[row * 256 + c0 + 1] + bh1);
    }
    grid_barrier_64();

    for (int b = 1; b < 32; b++) {
        const float* Hprev = Y + (size_t)(b - 1) * 65536;
        // stage A tile: sA[k][m] = Hprev[(rowBase+m)*256 + k]
        #pragma unroll 4
        for (int m = 0; m < 32; m++)
            sA[tid * 34 + m] = Hprev[(size_t)(rowBase + m) * 256 + tid];
        __syncthreads();

        float a00 = 0.f, a01 = 0.f, a10 = 0.f, a11 = 0.f;
        #pragma unroll 16
        for (int kk = 0; kk < 256; kk++) {
            float2 av = *(float2*)&sA[kk * 34 + ty * 2];
            float2 bv = *(float2*)&sB[kk * 34 + tx * 2];
            a00 += av.x * bv.x; a01 += av.x * bv.y;
            a10 += av.y * bv.x; a11 += av.y * bv.y;
        }

        const float* Ub = U + (size_t)b * 65536;
        float* Hout = Y + (size_t)b * 65536;
        {
            int row0 = rowBase + ty * 2, c0 = colBase + tx * 2;
            Hout[row0 * 256 + c0]           = tanhf(a00 + Ub[row0 * 256 + c0]           + bh0);
            Hout[row0 * 256 + c0 + 1]       = tanhf(a01 + Ub[row0 * 256 + c0 + 1]       + bh1);
            Hout[(row0 + 1) * 256 + c0]     = tanhf(a10 + Ub[(row0 + 1) * 256 + c0]     + bh0);
            Hout[(row0 + 1) * 256 + c0 + 1] = tanhf(a11 + Ub[(row0 + 1) * 256 + c0 + 1] + bh1);
        }
        grid_barrier_64();   // includes __syncthreads: safe to overwrite sA next iter
    }
}

// ---------- big-GEMM body: 128x64 tile, 8x4/thread, double-buffered ----------
template<bool BIAS>
__device__ __forceinline__ void gemm128_body(
    int K,
    const float* __restrict__ A, int lda,
    const float* __restrict__ Bm, int ldb,
    const float* __restrict__ bias,
    float* __restrict__ C, int ldc)
{
    __shared__ float As[2][16][136];
    __shared__ float Bs[2][16][72];
    int tid = threadIdx.x;
    int tx = tid & 15, ty = tid >> 4;
    int rowBase = blockIdx.y * 128, colBase = blockIdx.x * 64;

    int aRow = tid >> 1, aK = (tid & 1) << 3;     // 2 thr/row, 8 k-floats each
    int bK = tid >> 4, bN = (tid & 15) << 2;      // 16 k-rows x 16 n4-groups

    const float* Aptr = A + (size_t)(rowBase + aRow) * lda + aK;
    const float* Bptr = Bm + (size_t)bK * ldb + colBase + bN;

    float4 pa0 = *(const float4*)(Aptr);
    float4 pa1 = *(const float4*)(Aptr + 4);
    float4 pb  = *(const float4*)(Bptr);

    As[0][aK+0][aRow] = pa0.x; As[0][aK+1][aRow] = pa0.y;
    As[0][aK+2][aRow] = pa0.z; As[0][aK+3][aRow] = pa0.w;
    As[0][aK+4][aRow] = pa1.x; As[0][aK+5][aRow] = pa1.y;
    As[0][aK+6][aRow] = pa1.z; As[0][aK+7][aRow] = pa1.w;
    *(float4*)&Bs[0][bK][bN] = pb;
    __syncthreads();

    float acc[8][4];
    #pragma unroll
    for (int i = 0; i < 8; i++)
        #pragma unroll
        for (int j = 0; j < 4; j++) acc[i][j] = 0.f;

    int nt = K >> 4;
    for (int kt = 0; kt < nt; kt++) {
        int cur = kt & 1, nxt = cur ^ 1;
        if (kt + 1 < nt) {
            const float* Ap = Aptr + (kt + 1) * 16;
            pa0 = *(const float4*)(Ap);
            pa1 = *(const float4*)(Ap + 4);
            pb  = *(const float4*)(Bm + (size_t)((kt + 1) * 16 + bK) * ldb
                                   + colBase + bN);
        }
        #pragma unroll
        for (int kk = 0; kk < 16; kk++) {
            float4 b4 = *(float4*)&Bs[cur][kk][tx << 2];
            float4 a0 = *(float4*)&As[cur][kk][ty << 3];
            float4 a1 = *(float4*)&As[cur][kk][(ty << 3) + 4];
            float a[8] = {a0.x,a0.y,a0.z,a0.w,a1.x,a1.y,a1.z,a1.w};
            float b[4] = {b4.x,b4.y,b4.z,b4.w};
            #pragma unroll
            for (int i = 0; i < 8; i++)
                #pragma unroll
                for (int j = 0; j < 4; j++) acc[i][j] += a[i] * b[j];
        }
        if (kt + 1 < nt) {
            As[nxt][aK+0][aRow] = pa0.x; As[nxt][aK+1][aRow] = pa0.y;
            As[nxt][aK+2][aRow] = pa0.z; As[nxt][aK+3][aRow] = pa0.w;
            As[nxt][aK+4][aRow] = pa1.x; As[nxt][aK+5][aRow] = pa1.y;
            As[nxt][aK+6][aRow] = pa1.z; As[nxt][aK+7][aRow] = pa1.w;
            *(float4*)&Bs[nxt][bK][bN] = pb;
            __syncthreads();
        }
    }

    float bv[4] = {0.f, 0.f, 0.f, 0.f};
    if (BIAS) {
        #pragma unroll
        for (int j = 0; j < 4; j++) bv[j] = bias[colBase + (tx << 2) + j];
    }
    #pragma unroll
    for (int i = 0; i < 8; i++) {
        float4 ov = make_float4(acc[i][0] + bv[0], acc[i][1] + bv[1],
                                acc[i][2] + bv[2], acc[i][3] + bv[3]);
        *(float4*)&C[(size_t)(rowBase + (ty << 3) + i) * ldc
                     + colBase + (tx << 2)] = ov;
    }
}

// single GEMM (recon)
__global__ __launch_bounds__(256) void gemm128_one(
    int K, const float* __restrict__ A, int lda,
    const float* __restrict__ Bm, int ldb, const float* __restrict__ bias,
    float* __restrict__ C, int ldc)
{
    gemm128_body<true>(K, A, lda, Bm, ldb, bias, C, ldc);
}

// two GEMMs sharing A, no bias (xl/xr)
__global__ __launch_bounds__(256) void gemm128_z2(
    int K, const float* __restrict__ A, int lda,
    const float* __restrict__ B0, const float* __restrict__ B1, int ldb,
    float* __restrict__ C0, float* __restrict__ C1, int ldc)
{
    const float* Bm = blockIdx.z ? B1 : B0;
    float* C = blockIdx.z ? C1 : C0;
    gemm128_body<false>(K, A, lda, Bm, ldb, nullptr, C, ldc);
}

// three GEMMs sharing A, with bias (Q/K/V)
__global__ __launch_bounds__(256) void gemm128_z3(
    int K, const float* __restrict__ A, int lda,
    const float* __restrict__ B0, const float* __restrict__ B1,
    const float* __restrict__ B2, int ldb,
    const float* __restrict__ b0, const float* __restrict__ b1,
    const float* __restrict__ b2,
    float* __restrict__ C0, float* __restrict__ C1, float* __restrict__ C2,
    int ldc)
{
    int z = blockIdx.z;
    const float* Bm = (z == 0) ? B0 : (z == 1) ? B1 : B2;
    const float* bias = (z == 0) ? b0 : (z == 1) ? b1 : b2;
    float* C = (z == 0) ? C0 : (z == 1) ? C1 : C2;
    gemm128_body<true>(K, A, lda, Bm, ldb, bias, C, ldc);
}

// ---------- generic tiled GEMM (small/odd shapes) ----------
template<bool TRA, bool TRB, int ACT, bool FUSE>
__global__ __launch_bounds__(256) void gemm_k(
    int M, int N, int K,
    const float* __restrict__ A, int lda, int strideA,
    const float* __restrict__ Bm, int ldb,
    const float* __restrict__ bias,
    float* __restrict__ C, int ldc, int strideC,
    const float* __restrict__ w2, float* __restrict__ fpart)
{
    __shared__ float As[16][68];
    __shared__ float Bs[16][68];
    int tid = threadIdx.x;
    int tx = tid & 15, ty = tid >> 4;
    int bz = blockIdx.z;
    const float* Ab = A + (size_t)bz * strideA;
    int rowBase = blockIdx.y * 64, colBase = blockIdx.x * 64;
    float acc[4][4];
    #pragma unroll
    for (int i = 0; i < 4; i++)
        #pragma unroll
        for (int j = 0; j < 4; j++) acc[i][j] = 0.f;

    for (int k0 = 0; k0 < K; k0 += 16) {
        if (TRA) {
            int k = tid >> 4, m4 = (tid & 15) << 2;
            float4 va = *(const float4*)&Ab[(size_t)(k0 + k) * lda + rowBase + m4];
            *(float4*)&As[k][m4] = va;
        } else {
            int m = tid >> 2, k4 = (tid & 3) << 2;
            float4 va = *(const float4*)&Ab[(size_t)(rowBase + m) * lda + k0 + k4];
            As[k4+0][m] = va.x; As[k4+1][m] = va.y;
            As[k4+2][m] = va.z; As[k4+3][m] = va.w;
        }
        if (TRB) {
            int n = tid >> 2, k4 = (tid & 3) << 2;
            float4 vb = *(const float4*)&Bm[(size_t)(colBase + n) * ldb + k0 + k4];
            Bs[k4+0][n] = vb.x; Bs[k4+1][n] = vb.y;
            Bs[k4+2][n] = vb.z; Bs[k4+3][n] = vb.w;
        } else {
            int k = tid >> 4, n4 = (tid & 15) << 2;
            float4 vb = *(const float4*)&Bm[(size_t)(k0 + k) * ldb + colBase + n4];
            *(float4*)&Bs[k][n4] = vb;
        }
        __syncthreads();
        #pragma unroll
        for (int kk = 0; kk < 16; kk++) {
            float4 av = *(float4*)&As[kk][ty << 2];
            float4 bv = *(float4*)&Bs[kk][tx << 2];
            float a[4] = {av.x, av.y, av.z, av.w};
            float b[4] = {bv.x, bv.y, bv.z, bv.w};
            #pragma unroll
            for (int i = 0; i < 4; i++)
                #pragma unroll
                for (int j = 0; j < 4; j++) acc[i][j] += a[i] * b[j];
        }
        __syncthreads();
    }

    float bvals[4];
    #pragma unroll
    for (int j = 0; j < 4; j++) bvals[j] = bias ? bias[colBase + (tx << 2) + j] : 0.f;

    if (FUSE) {
        float wv[4];
        #pragma unroll
        for (int j = 0; j < 4; j++) wv[j] = w2[colBase + (tx << 2) + j];
        #pragma unroll
        for (int i = 0; i < 4; i++) {
            float p = 0.f;
            #pragma unroll
            for (int j = 0; j < 4; j++) {
                float vv = acc[i][j] + bvals[j];
                if (ACT == 1) vv = vv > 0.f ? vv : 0.f;
                p += vv * wv[j];
            }
            #pragma unroll
            for (int off = 8; off; off >>= 1)
                p += __shfl_down_sync(0xffffffffu, p, off, 16);
            if (tx == 0) {
                int elem = bz * 256 + rowBase + (ty << 2) + i;
                fpart[elem * 4 + blockIdx.x] = p;   // deterministic partial
            }
        }
    } else {
        float* Cb = C + (size_t)bz * strideC;
        #pragma unroll
        for (int i = 0; i < 4; i++) {
            float4 ov;
            float v0 = acc[i][0] + bvals[0];
            float v1 = acc[i][1] + bvals[1];
            float v2 = acc[i][2] + bvals[2];
            float v3 = acc[i][3] + bvals[3];
            if (ACT == 1) {
                v0 = v0 > 0.f ? v0 : 0.f; v1 = v1 > 0.f ? v1 : 0.f;
                v2 = v2 > 0.f ? v2 : 0.f; v3 = v3 > 0.f ? v3 : 0.f;
            }
            ov.x = v0; ov.y = v1; ov.z = v2; ov.w = v3;
            *(float4*)&Cb[(size_t)(rowBase + (ty << 2) + i) * ldc + colBase + (tx << 2)] = ov;
        }
    }
}

// deterministic forecast reduction: out[e] = b2 + sum_{j<4} fpart[e*4+j]
__global__ void forecast_reduce(const float* __restrict__ fpart,
                                const float* __restrict__ b2,
                                float* __restrict__ fout)
{
    int e = blockIdx.x * 256 + threadIdx.x;
    float4 p = *(const float4*)&fpart[e * 4];
    fout[e] = ((p.x + p.y) + (p.z + p.w)) + b2[0];
}

// ---------- GATv2 per-node: warp-parallel scores, barrier-free aggregate ----------
#define MAXDEG 1024
__global__ __launch_bounds__(256) void gat_node(
    const float* __restrict__ xl, const float* __restrict__ xr,
    const int* __restrict__ srcb, const int* __restrict__ offs,
    const int* __restrict__ elist, const float* __restrict__ att,
    const float* __restrict__ gbias, float* __restrict__ gatout,
    float* __restrict__ alpha)
{
    __shared__ int   srcs[MAXDEG + 1];
    __shared__ float ex0[MAXDEG + 1];
    __shared__ float ex1[MAXDEG + 1];
    __shared__ float xrs[512];

    int n = blockIdx.x;
    int g = n >> 8;
    int i = n & 255;
    int t = threadIdx.x;
    int lane = t & 31, warp = t >> 5;

    int beg = offs[i];
    int deg = offs[i + 1] - beg;
    int ne = deg + 1;                 // + self loop

    for (int e = t; e < deg; e += 256)
        srcs[e] = (g << 8) + srcb[elist[beg + e]];
    if (t == 0) srcs[deg] = n;        // self loop
    xrs[t]       = xr[(size_t)n * 512 + t];
    xrs[t + 256] = xr[(size_t)n * 512 + 256 + t];
    __syncthreads();

    for (int e = warp; e < ne; e += 8) {
        const float* xle = xl + (size_t)srcs[e] * 512;
        float p0 = 0.f, p1 = 0.f;
        #pragma unroll
        for (int ii = 0; ii < 8; ii++) {
            int c = lane + (ii << 5);
            float s0 = xle[c] + xrs[c];
            s0 = s0 > 0.f ? s0 : 0.2f * s0;
            p0 += s0 * att[c];
            float s1 = xle[c + 256] + xrs[c + 256];
            s1 = s1 > 0.f ? s1 : 0.2f * s1;
            p1 += s1 * att[c + 256];
        }
        #pragma unroll
        for (int off = 16; off; off >>= 1) {
            p0 += __shfl_down_sync(0xffffffffu, p0, off);
            p1 += __shfl_down_sync(0xffffffffu, p1, off);
        }
        if (lane == 0) {
            ex0[e] = __expf(p0);
            ex1[e] = __expf(p1);
        }
    }
    __syncthreads();

    float den0 = 0.f, den1 = 0.f;
    for (int e = 0; e < ne; e++) { den0 += ex0[e]; den1 += ex1[e]; }
    float inv0 = 1.f / den0, inv1 = 1.f / den1;

    float o0 = 0.f, o1 = 0.f;
    for (int e = 0; e < ne; e++) {
        const float* xle = xl + (size_t)srcs[e] * 512;
        o0 += ex0[e] * xle[t];
        o1 += ex1[e] * xle[t + 256];
    }
    gatout[(size_t)n * 512 + t]       = o0 * inv0 + gbias[t];
    gatout[(size_t)n * 512 + 256 + t] = o1 * inv1 + gbias[256 + t];

    for (int e = t; e < deg; e += 256) {
        int ei = (g << 12) + elist[beg + e];
        alpha[2 * ei]     = ex0[e] * inv0;
        alpha[2 * ei + 1] = ex1[e] * inv1;
    }
    if (t == 0) {
        int ei = 131072 + n;          // self-loop edge index
        alpha[2 * ei]     = ex0[deg] * inv0;
        alpha[2 * ei + 1] = ex1[deg] * inv1;
    }
}

// ---------- fused MHA core: per (b,h) block; single-pass online softmax ----------
__global__ __launch_bounds__(256, 1) void attn_kernel(
    const float* __restrict__ q, const float* __restrict__ kbuf,
    const float* __restrict__ vbuf, float* __restrict__ outb)
{
    __shared__ float Ks[64 * 64];
    __shared__ float Vs[64 * 64];
    int bh = blockIdx.x;
    int b = bh >> 2, h = bh & 3;
    int s = threadIdx.x;
    size_t qoff = ((size_t)(b * 256 + s)) * 256 + h * 64;

    float qr[64];
    #pragma unroll
    for (int d4 = 0; d4 < 16; d4++) {
        float4 v = *(const float4*)&q[qoff + d4 * 4];
        qr[d4*4] = v.x; qr[d4*4+1] = v.y; qr[d4*4+2] = v.z; qr[d4*4+3] = v.w;
    }
    float acc[64];
    #pragma unroll
    for (int d = 0; d < 64; d++) acc[d] = 0.f;
    float den = 0.f;

    for (int t0 = 0; t0 < 256; t0 += 64) {
        __syncthreads();
        #pragma unroll
        for (int r = 0; r < 4; r++) {
            int idx = r * 256 + threadIdx.x;
            int tt = idx >> 4, d4 = (idx & 15) << 2;
            size_t go = ((size_t)(b * 256 + t0 + tt)) * 256 + h * 64 + d4;
            *(float4*)&Ks[tt * 64 + d4] = *(const float4*)&kbuf[go];
            *(float4*)&Vs[tt * 64 + d4] = *(const float4*)&vbuf[go];
        }
        __syncthreads();
        for (int tt = 0; tt < 64; tt++) {
            float dot = 0.f;
            #pragma unroll
            for (int d4 = 0; d4 < 16; d4++) {
                float4 kv = *(float4*)&Ks[tt * 64 + d4 * 4];
                dot += qr[d4*4] * kv.x + qr[d4*4+1] * kv.y
                     + qr[d4*4+2] * kv.z + qr[d4*4+3] * kv.w;
            }
            float e = __expf(dot * 0.125f);   // 1/sqrt(64)
            den += e;
            #pragma unroll
            for (int d4 = 0; d4 < 16; d4++) {
                float4 vv = *(float4*)&Vs[tt * 64 + d4 * 4];
                acc[d4*4]   += e * vv.x;
                acc[d4*4+1] += e * vv.y;
                acc[d4*4+2] += e * vv.z;
                acc[d4*4+3] += e * vv.w;
            }
        }
    }
    float inv = 1.f / den;
    #pragma unroll
    for (int d4 = 0; d4 < 16; d4++) {
        float4 ov = make_float4(acc[d4*4] * inv, acc[d4*4+1] * inv,
                                acc[d4*4+2] * inv, acc[d4*4+3] * inv);
        *(float4*)&outb[qoff + d4 * 4] = ov;
    }
}

// ---------- launch ----------
extern "C" void kernel_launch(void* const* d_in, const int* in_sizes, int n_in,
                              void* d_out, int out_size)
{
    const float* x    = (const float*)d_in[0];
    const int*   eidx = (const int*)  d_in[1];
    const float* Wih  = (const float*)d_in[2];
    const float* bih  = (const float*)d_in[3];
    const float* Whh  = (const float*)d_in[4];
    const float* bhh  = (const float*)d_in[5];
    const float* Wl   = (const float*)d_in[6];
    const float* Wr   = (const float*)d_in[7];
    const float* att  = (const float*)d_in[8];
    const float* gbias= (const float*)d_in[9];
    const float* Wq   = (const float*)d_in[10];
    const float* bq   = (const float*)d_in[11];
    const float* Wk   = (const float*)d_in[12];
    const float* bk   = (const float*)d_in[13];
    const float* Wv   = (const float*)d_in[14];
    const float* bv   = (const float*)d_in[15];
    const float* Wo   = (const float*)d_in[16];
    const float* bo   = (const float*)d_in[17];
    const float* W1   = (const float*)d_in[18];
    const float* b1   = (const float*)d_in[19];
    const float* W2   = (const float*)d_in[20];
    const float* b2   = (const float*)d_in[21];
    float* out = (float*)d_out;

    float *u, *y, *xl, *xr, *gat, *q, *k, *v, *attn, *fpart;
    int *offs, *elist;
    cudaGetSymbolAddress((void**)&u,    g_u);
    cudaGetSymbolAddress((void**)&y,    g_y);
    cudaGetSymbolAddress((void**)&xl,   g_xl);
    cudaGetSymbolAddress((void**)&xr,   g_xr);
    cudaGetSymbolAddress((void**)&gat,  g_gat);
    cudaGetSymbolAddress((void**)&q,    g_q);
    cudaGetSymbolAddress((void**)&k,    g_k);
    cudaGetSymbolAddress((void**)&v,    g_v);
    cudaGetSymbolAddress((void**)&attn, g_attn);
    cudaGetSymbolAddress((void**)&fpart,g_fpart);
    cudaGetSymbolAddress((void**)&offs, g_offs);
    cudaGetSymbolAddress((void**)&elist,g_elist);

    // 1. CSR of base graph (same structure for all 32 graphs)
    build_csr<<<1, 256>>>(eidx, offs, elist);

    // 2a. Parallel RNN input projection: U[b] = xp[b] @ Wih^T + bih
    gemm_k<true,true,0,false><<<dim3(4, 4, 32), 256>>>(256, 256, 128,
        x, 256, 32768, Wih, 128, bih, u, 256, 65536, nullptr, nullptr);

    // 2b. Persistent recurrent scan (single kernel, software grid barrier).
    //     Attribute set unconditionally (idempotent; no static guards).
    const int rnn_smem = 2 * 256 * 34 * sizeof(float);   // 69632 B
    cudaFuncSetAttribute(rnn_scan,
        cudaFuncAttributeMaxDynamicSharedMemorySize, rnn_smem);
    rnn_scan<<<RNN_BLOCKS, 256, rnn_smem>>>(u, Whh, bhh, y);

    // 3. GAT linear transforms (merged): xl/xr = nodes @ Wl/Wr
    gemm128_z2<<<dim3(8, 64, 2), 256>>>(256, y, 256, Wl, Wr, 512, xl, xr, 512);

    // 4. GAT edge softmax + aggregation (writes gatout and alpha output)
    gat_node<<<8192, 256>>>(xl, xr, eidx, offs, elist, att, gbias,
                            gat, out + ALPHA_OFF);

    // 5. Q/K/V projections (merged) on Z = gatout reinterpreted [16384,256]
    gemm128_z3<<<dim3(4, 128, 3), 256>>>(256, gat, 256, Wq, Wk, Wv, 256,
                                         bq, bk, bv, q, k, v, 256);

    // 6. fused softmax(QK^T/8) @ V   (64 batches x 4 heads)
    attn_kernel<<<256, 256>>>(q, k, v, attn);

    // 7. recon = attn @ Wo + bo  -> d_out[0 : 4194304]
    gemm128_one<<<dim3(4, 128), 256>>>(256, attn, 256, Wo, 256, bo, out, 256);

    // 8. forecast = relu(z^T @ W1 + b1) @ W2 + b2 -> d_out[4194304 : +16384]
    gemm_k<true,false,1,true><<<dim3(4, 4, 64), 256>>>(256, 256, 256,
        gat, 256, 65536, W1, 256, b1, nullptr, 0, 0, W2, fpart);
    forecast_reduce<<<64, 256>>>(fpart, b2, out + FORECAST_OFF);
}

// round 16
// speedup vs baseline: 1.0647x; 1.0647x over previous
#include <cuda_runtime.h>
#include <math.h>

// ---------- problem constants ----------
#define RECON_ELEMS 4194304 // 64*256*256
#define FORECAST_OFF RECON_ELEMS
#define ALPHA_OFF   (RECON_ELEMS + 16384)

// ---------- scratch (static __device__, no allocations) ----------
__device__ float g_u[2097152];     // RNN input-proj U [32,256,256]
__device__ float g_y[2097152];     // RNN outputs [32,256,256] == nodes [8192,256]
__device__ float g_xl[4194304];    // [8192,512]
__device__ float g_xr[4194304];    // [8192,512]
__device__ float g_gat[4194304];   // [8192,512] == Z [16384,256]
__device__ float g_q[4194304];     // [16384,256]
__device__ float g_k[4194304];
__device__ float g_v[4194304];
__device__ float g_attn[4194304];  // [16384,256]
__device__ float g_fpart[65536];   // forecast partials [16384 elems][4 tiles]
__device__ int   g_offs[257];
__device__ int   g_elist[4096];

// ---------- CSR build (deterministic, stable order) ----------
__global__ __launch_bounds__(256) void build_csr(const int* __restrict__ eidx,
                                                 int* __restrict__ offs,
                                                 int* __restrict__ elist)
{
    __shared__ int dsts[4096];
    __shared__ int cnt[256];
    __shared__ int off_s[257];
    int t = threadIdx.x;
    const int* dst = eidx + 4096;   // edge_idx[0][1][:]
    for (int j = t; j < 4096; j += 256) dsts[j] = dst[j];
    cnt[t] = 0;
    __syncthreads();
    for (int j = t; j < 4096; j += 256) atomicAdd(&cnt[dsts[j]], 1);
    __syncthreads();
    if (t == 0) {
        int run = 0;
        for (int i = 0; i < 256; i++) { off_s[i] = run; run += cnt[i]; }
        off_s[256] = run;
    }
    __syncthreads();
    offs[t] = off_s[t];
    if (t == 0) offs[256] = off_s[256];
    // stable fill: thread t owns destination value t; scans edges in j order
    int pos = off_s[t];
    for (int j = 0; j < 4096; j++) {
        if (dsts[j] == t) elist[pos++] = j;
    }
}

// ---------- RNN step v2: full-tile staging, ONE barrier, 256-deep inner ----------
// H = tanh( U_b + Hprev @ Whh^T + bhh ).  64 blocks, 32x32 outputs each.
// sA[k][m] = Hprev[rowBase+m][k], sB[k][n] = Whh[colBase+n][k], padded rows (34).
__global__ __launch_bounds__(256) void rnn_step2(
    const float* __restrict__ Ub,     // [256,256]
    const float* __restrict__ Hprev,  // [256,256] or nullptr (step 0)
    const float* __restrict__ Whh,    // [256,256]
    const float* __restrict__ bhh,    // [256]
    float* __restrict__ Hout)         // [256,256]
{
    extern __shared__ float sm2[];
    float* sA = sm2;                  // [256][34]
    float* sB = sm2 + 256 * 34;       // [256][34]
    int tid = threadIdx.x;
    int tx = tid & 15, ty = tid >> 4;
    int rowBase = (blockIdx.x >> 3) * 32;
    int colBase = (blockIdx.x & 7) * 32;

    float bh0 = bhh[colBase + tx * 2];
    float bh1 = bhh[colBase + tx * 2 + 1];

    if (Hprev == nullptr) {           // step 0: H0 = tanh(U0 + bhh)
        #pragma unroll
        for (int i = 0; i < 2; i++) {
            int row = rowBase + ty * 2 + i;
            int c0 = colBase + tx * 2;
            Hout[row * 256 + c0]     = tanhf(Ub[row * 256 + c0]     + bh0);
            Hout[row * 256 + c0 + 1] = tanhf(Ub[row * 256 + c0 + 1] + bh1);
        }
        return;
    }

    // stage both tiles (independent loads, one barrier total)
    #pragma unroll 8
    for (int m = 0; m < 32; m++)
        sA[tid * 34 + m] = Hprev[(size_t)(rowBase + m) * 256 + tid];
    #pragma unroll 8
    for (int n = 0; n < 32; n++)
        sB[tid * 34 + n] = Whh[(size_t)(colBase + n) * 256 + tid];
    __syncthreads();

    float a00 = 0.f, a01 = 0.f, a10 = 0.f, a11 = 0.f;
    #pragma unroll 16
    for (int kk = 0; kk < 256; kk++) {
        float2 av = *(float2*)&sA[kk * 34 + ty * 2];
        float2 bv = *(float2*)&sB[kk * 34 + tx * 2];
        a00 += av.x * bv.x; a01 += av.x * bv.y;
        a10 += av.y * bv.x; a11 += av.y * bv.y;
    }

    int row0 = rowBase + ty * 2, c0 = colBase + tx * 2;
    Hout[row0 * 256 + c0]           = tanhf(a00 + Ub[row0 * 256 + c0]           + bh0);
    Hout[row0 * 256 + c0 + 1]       = tanhf(a01 + Ub[row0 * 256 + c0 + 1]       + bh1);
    Hout[(row0 + 1) * 256 + c0]     = tanhf(a10 + Ub[(row0 + 1) * 256 + c0]     + bh0);
    Hout[(row0 + 1) * 256 + c0 + 1] = tanhf(a11 + Ub[(row0 + 1) * 256 + c0 + 1] + bh1);
}

// ---------- big-GEMM body: 128x64 tile, 8x4/thread, double-buffered ----------
template<bool BIAS>
__device__ __forceinline__ void gemm128_body(
    int K,
    const float* __restrict__ A, int lda,
    const float* __restrict__ Bm, int ldb,
    const float* __restrict__ bias,
    float* __restrict__ C, int ldc)
{
    __shared__ float As[2][16][136];
    __shared__ float Bs[2][16][72];
    int tid = threadIdx.x;
    int tx = tid & 15, ty = tid >> 4;
    int rowBase = blockIdx.y * 128, colBase = blockIdx.x * 64;

    int aRow = tid >> 1, aK = (tid & 1) << 3;     // 2 thr/row, 8 k-floats each
    int bK = tid >> 4, bN = (tid & 15) << 2;      // 16 k-rows x 16 n4-groups

    const float* Aptr = A + (size_t)(rowBase + aRow) * lda + aK;
    const float* Bptr = Bm + (size_t)bK * ldb + colBase + bN;

    float4 pa0 = *(const float4*)(Aptr);
    float4 pa1 = *(const float4*)(Aptr + 4);
    float4 pb  = *(const float4*)(Bptr);

    As[0][aK+0][aRow] = pa0.x; As[0][aK+1][aRow] = pa0.y;
    As[0][aK+2][aRow] = pa0.z; As[0][aK+3][aRow] = pa0.w;
    As[0][aK+4][aRow] = pa1.x; As[0][aK+5][aRow] = pa1.y;
    As[0][aK+6][aRow] = pa1.z; As[0][aK+7][aRow] = pa1.w;
    *(float4*)&Bs[0][bK][bN] = pb;
    __syncthreads();

    float acc[8][4];
    #pragma unroll
    for (int i = 0; i < 8; i++)
        #pragma unroll
        for (int j = 0; j < 4; j++) acc[i][j] = 0.f;

    int nt = K >> 4;
    for (int kt = 0; kt < nt; kt++) {
        int cur = kt & 1, nxt = cur ^ 1;
        if (kt + 1 < nt) {
            const float* Ap = Aptr + (kt + 1) * 16;
            pa0 = *(const float4*)(Ap);
            pa1 = *(const float4*)(Ap + 4);
            pb  = *(const float4*)(Bm + (size_t)((kt + 1) * 16 + bK) * ldb
                                   + colBase + bN);
        }
        #pragma unroll
        for (int kk = 0; kk < 16; kk++) {
            float4 b4 = *(float4*)&Bs[cur][kk][tx << 2];
            float4 a0 = *(float4*)&As[cur][kk][ty << 3];
            float4 a1 = *(float4*)&As[cur][kk][(ty << 3) + 4];
            float a[8] = {a0.x,a0.y,a0.z,a0.w,a1.x,a1.y,a1.z,a1.w};
            float b[4] = {b4.x,b4.y,b4.z,b4.w};
            #pragma unroll
            for (int i = 0; i < 8; i++)
                #pragma unroll
                for (int j = 0; j < 4; j++) acc[i][j] += a[i] * b[j];
        }
        if (kt + 1 < nt) {
            As[nxt][aK+0][aRow] = pa0.x; As[nxt][aK+1][aRow] = pa0.y;
            As[nxt][aK+2][aRow] = pa0.z; As[nxt][aK+3][aRow] = pa0.w;
            As[nxt][aK+4][aRow] = pa1.x; As[nxt][aK+5][aRow] = pa1.y;
            As[nxt][aK+6][aRow] = pa1.z; As[nxt][aK+7][aRow] = pa1.w;
            *(float4*)&Bs[nxt][bK][bN] = pb;
            __syncthreads();
        }
    }

    float bv[4] = {0.f, 0.f, 0.f, 0.f};
    if (BIAS) {
        #pragma unroll
        for (int j = 0; j < 4; j++) bv[j] = bias[colBase + (tx << 2) + j];
    }
    #pragma unroll
    for (int i = 0; i < 8; i++) {
        float4 ov = make_float4(acc[i][0] + bv[0], acc[i][1] + bv[1],
                                acc[i][2] + bv[2], acc[i][3] + bv[3]);
        *(float4*)&C[(size_t)(rowBase + (ty << 3) + i) * ldc
                     + colBase + (tx << 2)] = ov;
    }
}

// single GEMM (recon)
__global__ __launch_bounds__(256) void gemm128_one(
    int K, const float* __restrict__ A, int lda,
    const float* __restrict__ Bm, int ldb, const float* __restrict__ bias,
    float* __restrict__ C, int ldc)
{
    gemm128_body<true>(K, A, lda, Bm, ldb, bias, C, ldc);
}

// two GEMMs sharing A, no bias (xl/xr)
__global__ __launch_bounds__(256) void gemm128_z2(
    int K, const float* __restrict__ A, int lda,
    const float* __restrict__ B0, const float* __restrict__ B1, int ldb,
    float* __restrict__ C0, float* __restrict__ C1, int ldc)
{
    const float* Bm = blockIdx.z ? B1 : B0;
    float* C = blockIdx.z ? C1 : C0;
    gemm128_body<false>(K, A, lda, Bm, ldb, nullptr, C, ldc);
}

// three GEMMs sharing A, with bias (Q/K/V)
__global__ __launch_bounds__(256) void gemm128_z3(
    int K, const float* __restrict__ A, int lda,
    const float* __restrict__ B0, const float* __restrict__ B1,
    const float* __restrict__ B2, int ldb,
    const float* __restrict__ b0, const float* __restrict__ b1,
    const float* __restrict__ b2,
    float* __restrict__ C0, float* __restrict__ C1, float* __restrict__ C2,
    int ldc)
{
    int z = blockIdx.z;
    const float* Bm = (z == 0) ? B0 : (z == 1) ? B1 : B2;
    const float* bias = (z == 0) ? b0 : (z == 1) ? b1 : b2;
    float* C = (z == 0) ? C0 : (z == 1) ? C1 : C2;
    gemm128_body<true>(K, A, lda, Bm, ldb, bias, C, ldc);
}

// ---------- MLP forecast GEMM: TRA (A=[K,M] per batch), 128x64 tile,
// double-buffered, fused relu -> dot(w2) -> deterministic fpart write ----------
__global__ __launch_bounds__(256) void gemm128_mlp(
    const float* __restrict__ Zbase,  // [64 batches][K=256][M=256]
    const float* __restrict__ W1,     // [256,256] row-major [K][N]
    const float* __restrict__ b1,     // [256]
    const float* __restrict__ w2,     // [256]
    float* __restrict__ fpart)        // [16384][4]
{
    __shared__ float As[2][16][136];
    __shared__ float Bs[2][16][72];
    int tid = threadIdx.x;
    int tx = tid & 15, ty = tid >> 4;
    int batch = blockIdx.y >> 1;
    int mBase = (blockIdx.y & 1) * 128;
    int colBase = blockIdx.x * 64;
    const float* A = Zbase + (size_t)batch * 65536;   // A[k][m], lda=256

    // A slice: 16 k x 128 m -> 2 float4 per thread, coalesced along m
    int aIdx0 = tid, aIdx1 = tid + 256;
    int ak0 = aIdx0 >> 5, am0 = (aIdx0 & 31) << 2;
    int ak1 = aIdx1 >> 5, am1 = (aIdx1 & 31) << 2;
    int bK = tid >> 4, bN = (tid & 15) << 2;

    float4 pa0 = *(const float4*)&A[(size_t)ak0 * 256 + mBase + am0];
    float4 pa1 = *(const float4*)&A[(size_t)ak1 * 256 + mBase + am1];
    float4 pb  = *(const float4*)&W1[(size_t)bK * 256 + colBase + bN];

    *(float4*)&As[0][ak0][am0] = pa0;
    *(float4*)&As[0][ak1][am1] = pa1;
    *(float4*)&Bs[0][bK][bN] = pb;
    __syncthreads();

    float acc[8][4];
    #pragma unroll
    for (int i = 0; i < 8; i++)
        #pragma unroll
        for (int j = 0; j < 4; j++) acc[i][j] = 0.f;

    for (int kt = 0; kt < 16; kt++) {
        int cur = kt & 1, nxt = cur ^ 1;
        if (kt + 1 < 16) {
            int k0 = (kt + 1) * 16;
            pa0 = *(const float4*)&A[(size_t)(k0 + ak0) * 256 + mBase + am0];
            pa1 = *(const float4*)&A[(size_t)(k0 + ak1) * 256 + mBase + am1];
            pb  = *(const float4*)&W1[(size_t)(k0 + bK) * 256 + colBase + bN];
        }
        #pragma unroll
        for (int kk = 0; kk < 16; kk++) {
            float4 b4 = *(float4*)&Bs[cur][kk][tx << 2];
            float4 a0 = *(float4*)&As[cur][kk][ty << 3];
            float4 a1 = *(float4*)&As[cur][kk][(ty << 3) + 4];
            float a[8] = {a0.x,a0.y,a0.z,a0.w,a1.x,a1.y,a1.z,a1.w};
            float b[4] = {b4.x,b4.y,b4.z,b4.w};
            #pragma unroll
            for (int i = 0; i < 8; i++)
                #pragma unroll
                for (int j = 0; j < 4; j++) acc[i][j] += a[i] * b[j];
        }
        if (kt + 1 < 16) {
            *(float4*)&As[nxt][ak0][am0] = pa0;
            *(float4*)&As[nxt][ak1][am1] = pa1;
            *(float4*)&Bs[nxt][bK][bN] = pb;
            __syncthreads();
        }
    }

    float bvals[4], wv[4];
    #pragma unroll
    for (int j = 0; j < 4; j++) {
        bvals[j] = b1[colBase + (tx << 2) + j];
        wv[j]    = w2[colBase + (tx << 2) + j];
    }
    #pragma unroll
    for (int i = 0; i < 8; i++) {
        float p = 0.f;
        #pragma unroll
        for (int j = 0; j < 4; j++) {
            float vv = acc[i][j] + bvals[j];
            vv = vv > 0.f ? vv : 0.f;
            p += vv * wv[j];
        }
        #pragma unroll
        for (int off = 8; off; off >>= 1)
            p += __shfl_down_sync(0xffffffffu, p, off, 16);
        if (tx == 0) {
            int elem = batch * 256 + mBase + (ty << 3) + i;
            fpart[elem * 4 + blockIdx.x] = p;
        }
    }
}

// ---------- generic tiled GEMM (U projection only) ----------
template<bool TRA, bool TRB>
__global__ __launch_bounds__(256) void gemm_k(
    int M, int N, int K,
    const float* __restrict__ A, int lda, int strideA,
    const float* __restrict__ Bm, int ldb,
    const float* __restrict__ bias,
    float* __restrict__ C, int ldc, int strideC)
{
    __shared__ float As[16][68];
    __shared__ float Bs[16][68];
    int tid = threadIdx.x;
    int tx = tid & 15, ty = tid >> 4;
    int bz = blockIdx.z;
    const float* Ab = A + (size_t)bz * strideA;
    int rowBase = blockIdx.y * 64, colBase = blockIdx.x * 64;
    float acc[4][4];
    #pragma unroll
    for (int i = 0; i < 4; i++)
        #pragma unroll
        for (int j = 0; j < 4; j++) acc[i][j] = 0.f;

    for (int k0 = 0; k0 < K; k0 += 16) {
        if (TRA) {
            int k = tid >> 4, m4 = (tid & 15) << 2;
            float4 va = *(const float4*)&Ab[(size_t)(k0 + k) * lda + rowBase + m4];
            *(float4*)&As[k][m4] = va;
        } else {
            int m = tid >> 2, k4 = (tid & 3) << 2;
            float4 va = *(const float4*)&Ab[(size_t)(rowBase + m) * lda + k0 + k4];
            As[k4+0][m] = va.x; As[k4+1][m] = va.y;
            As[k4+2][m] = va.z; As[k4+3][m] = va.w;
        }
        if (TRB) {
            int n = tid >> 2, k4 = (tid & 3) << 2;
            float4 vb = *(const float4*)&Bm[(size_t)(colBase + n) * ldb + k0 + k4];
            Bs[k4+0][n] = vb.x; Bs[k4+1][n] = vb.y;
            Bs[k4+2][n] = vb.z; Bs[k4+3][n] = vb.w;
        } else {
            int k = tid >> 4, n4 = (tid & 15) << 2;
            float4 vb = *(const float4*)&Bm[(size_t)(k0 + k) * ldb + colBase + n4];
            *(float4*)&Bs[k][n4] = vb;
        }
        __syncthreads();
        #pragma unroll
        for (int kk = 0; kk < 16; kk++) {
            float4 av = *(float4*)&As[kk][ty << 2];
            float4 bv = *(float4*)&Bs[kk][tx << 2];
            float a[4] = {av.x, av.y, av.z, av.w};
            float b[4] = {bv.x, bv.y, bv.z, bv.w};
            #pragma unroll
            for (int i = 0; i < 4; i++)
                #pragma unroll
                for (int j = 0; j < 4; j++) acc[i][j] += a[i] * b[j];
        }
        __syncthreads();
    }

    float bvals[4];
    #pragma unroll
    for (int j = 0; j < 4; j++) bvals[j] = bias ? bias[colBase + (tx << 2) + j] : 0.f;

    float* Cb = C + (size_t)bz * strideC;
    #pragma unroll
    for (int i = 0; i < 4; i++) {
        float4 ov = make_float4(acc[i][0] + bvals[0], acc[i][1] + bvals[1],
                                acc[i][2] + bvals[2], acc[i][3] + bvals[3]);
        *(float4*)&Cb[(size_t)(rowBase + (ty << 2) + i) * ldc + colBase + (tx << 2)] = ov;
    }
}

// deterministic forecast reduction: out[e] = b2 + sum_{j<4} fpart[e*4+j]
__global__ void forecast_reduce(const float* __restrict__ fpart,
                                const float* __restrict__ b2,
                                float* __restrict__ fout)
{
    int e = blockIdx.x * 256 + threadIdx.x;
    float4 p = *(const float4*)&fpart[e * 4];
    fout[e] = ((p.x + p.y) + (p.z + p.w)) + b2[0];
}

// ---------- GATv2 per-node: warp-parallel scores, barrier-free aggregate ----------
#define MAXDEG 1024
__global__ __launch_bounds__(256) void gat_node(
    const float* __restrict__ xl, const float* __restrict__ xr,
    const int* __restrict__ srcb, const int* __restrict__ offs,
    const int* __restrict__ elist, const float* __restrict__ att,
    const float* __restrict__ gbias, float* __restrict__ gatout,
    float* __restrict__ alpha)
{
    __shared__ int   srcs[MAXDEG + 1];
    __shared__ float ex0[MAXDEG + 1];
    __shared__ float ex1[MAXDEG + 1];
    __shared__ float xrs[512];

    int n = blockIdx.x;
    int g = n >> 8;
    int i = n & 255;
    int t = threadIdx.x;
    int lane = t & 31, warp = t >> 5;

    int beg = offs[i];
    int deg = offs[i + 1] - beg;
    int ne = deg + 1;                 // + self loop

    for (int e = t; e < deg; e += 256)
        srcs[e] = (g << 8) + srcb[elist[beg + e]];
    if (t == 0) srcs[deg] = n;        // self loop
    xrs[t]       = xr[(size_t)n * 512 + t];
    xrs[t + 256] = xr[(size_t)n * 512 + 256 + t];
    __syncthreads();

    for (int e = warp; e < ne; e += 8) {
        const float* xle = xl + (size_t)srcs[e] * 512;
        float p0 = 0.f, p1 = 0.f;
        #pragma unroll
        for (int ii = 0; ii < 8; ii++) {
            int c = lane + (ii << 5);
            float s0 = xle[c] + xrs[c];
            s0 = s0 > 0.f ? s0 : 0.2f * s0;
            p0 += s0 * att[c];
            float s1 = xle[c + 256] + xrs[c + 256];
            s1 = s1 > 0.f ? s1 : 0.2f * s1;
            p1 += s1 * att[c + 256];
        }
        #pragma unroll
        for (int off = 16; off; off >>= 1) {
            p0 += __shfl_down_sync(0xffffffffu, p0, off);
            p1 += __shfl_down_sync(0xffffffffu, p1, off);
        }
        if (lane == 0) {
            ex0[e] = __expf(p0);
            ex1[e] = __expf(p1);
        }
    }
    __syncthreads();

    float den0 = 0.f, den1 = 0.f;
    for (int e = 0; e < ne; e++) { den0 += ex0[e]; den1 += ex1[e]; }
    float inv0 = 1.f / den0, inv1 = 1.f / den1;

    float o0 = 0.f, o1 = 0.f;
    for (int e = 0; e < ne; e++) {
        const float* xle = xl + (size_t)srcs[e] * 512;
        o0 += ex0[e] * xle[t];
        o1 += ex1[e] * xle[t + 256];
    }
    gatout[(size_t)n * 512 + t]       = o0 * inv0 + gbias[t];
    gatout[(size_t)n * 512 + 256 + t] = o1 * inv1 + gbias[256 + t];

    for (int e = t; e < deg; e += 256) {
        int ei = (g << 12) + elist[beg + e];
        alpha[2 * ei]     = ex0[e] * inv0;
        alpha[2 * ei + 1] = ex1[e] * inv1;
    }
    if (t == 0) {
        int ei = 131072 + n;          // self-loop edge index
        alpha[2 * ei]     = ex0[deg] * inv0;
        alpha[2 * ei + 1] = ex1[deg] * inv1;
    }
}

// ---------- fused MHA core: per (b,h) block; 4-way split dot chains ----------
__global__ __launch_bounds__(256, 1) void attn_kernel(
    const float* __restrict__ q, const float* __restrict__ kbuf,
    const float* __restrict__ vbuf, float* __restrict__ outb)
{
    __shared__ float Ks[64 * 64];
    __shared__ float Vs[64 * 64];
    int bh = blockIdx.x;
    int b = bh >> 2, h = bh & 3;
    int s = threadIdx.x;
    size_t qoff = ((size_t)(b * 256 + s)) * 256 + h * 64;

    float qr[64];
    #pragma unroll
    for (int d4 = 0; d4 < 16; d4++) {
        float4 v = *(const float4*)&q[qoff + d4 * 4];
        qr[d4*4] = v.x; qr[d4*4+1] = v.y; qr[d4*4+2] = v.z; qr[d4*4+3] = v.w;
    }
    float acc[64];
    #pragma unroll
    for (int d = 0; d < 64; d++) acc[d] = 0.f;
    float den = 0.f;

    for (int t0 = 0; t0 < 256; t0 += 64) {
        __syncthreads();
        #pragma unroll
        for (int r = 0; r < 4; r++) {
            int idx = r * 256 + threadIdx.x;
            int tt = idx >> 4, d4 = (idx & 15) << 2;
            size_t go = ((size_t)(b * 256 + t0 + tt)) * 256 + h * 64 + d4;
            *(float4*)&Ks[tt * 64 + d4] = *(const float4*)&kbuf[go];
            *(float4*)&Vs[tt * 64 + d4] = *(const float4*)&vbuf[go];
        }
        __syncthreads();
        for (int tt = 0; tt < 64; tt++) {
            float d0 = 0.f, d1 = 0.f, d2 = 0.f, d3 = 0.f;
            #pragma unroll
            for (int d4 = 0; d4 < 16; d4 += 4) {
                float4 k0 = *(float4*)&Ks[tt * 64 + d4 * 4];
                float4 k1 = *(float4*)&Ks[tt * 64 + d4 * 4 + 4];
                float4 k2 = *(float4*)&Ks[tt * 64 + d4 * 4 + 8];
                float4 k3 = *(float4*)&Ks[tt * 64 + d4 * 4 + 12];
                d0 += qr[d4*4]   * k0.x + qr[d4*4+1] * k0.y
                    + qr[d4*4+2] * k0.z + qr[d4*4+3] * k0.w;
                d1 += qr[d4*4+4] * k1.x + qr[d4*4+5] * k1.y
                    + qr[d4*4+6] * k1.z + qr[d4*4+7] * k1.w;
                d2 += qr[d4*4+8] * k2.x + qr[d4*4+9] * k2.y
                    + qr[d4*4+10]* k2.z + qr[d4*4+11]* k2.w;
                d3 += qr[d4*4+12]* k3.x + qr[d4*4+13]* k3.y
                    + qr[d4*4+14]* k3.z + qr[d4*4+15]* k3.w;
            }
            float dot = (d0 + d1) + (d2 + d3);
            float e = __expf(dot * 0.125f);   // 1/sqrt(64)
            den += e;
            #pragma unroll
            for (int d4 = 0; d4 < 16; d4++) {
                float4 vv = *(float4*)&Vs[tt * 64 + d4 * 4];
                acc[d4*4]   += e * vv.x;
                acc[d4*4+1] += e * vv.y;
                acc[d4*4+2] += e * vv.z;
                acc[d4*4+3] += e * vv.w;
            }
        }
    }
    float inv = 1.f / den;
    #pragma unroll
    for (int d4 = 0; d4 < 16; d4++) {
        float4 ov = make_float4(acc[d4*4] * inv, acc[d4*4+1] * inv,
                                acc[d4*4+2] * inv, acc[d4*4+3] * inv);
        *(float4*)&outb[qoff + d4 * 4] = ov;
    }
}

// ---------- launch ----------
extern "C" void kernel_launch(void* const* d_in, const int* in_sizes, int n_in,
                              void* d_out, int out_size)
{
    const float* x    = (const float*)d_in[0];
    const int*   eidx = (const int*)  d_in[1];
    const float* Wih  = (const float*)d_in[2];
    const float* bih  = (const float*)d_in[3];
    const float* Whh  = (const float*)d_in[4];
    const float* bhh  = (const float*)d_in[5];
    const float* Wl   = (const float*)d_in[6];
    const float* Wr   = (const float*)d_in[7];
    const float* att  = (const float*)d_in[8];
    const float* gbias= (const float*)d_in[9];
    const float* Wq   = (const float*)d_in[10];
    const float* bq   = (const float*)d_in[11];
    const float* Wk   = (const float*)d_in[12];
    const float* bk   = (const float*)d_in[13];
    const float* Wv   = (const float*)d_in[14];
    const float* bv   = (const float*)d_in[15];
    const float* Wo   = (const float*)d_in[16];
    const float* bo   = (const float*)d_in[17];
    const float* W1   = (const float*)d_in[18];
    const float* b1   = (const float*)d_in[19];
    const float* W2   = (const float*)d_in[20];
    const float* b2   = (const float*)d_in[21];
    float* out = (float*)d_out;

    float *u, *y, *xl, *xr, *gat, *q, *k, *v, *attn, *fpart;
    int *offs, *elist;
    cudaGetSymbolAddress((void**)&u,    g_u);
    cudaGetSymbolAddress((void**)&y,    g_y);
    cudaGetSymbolAddress((void**)&xl,   g_xl);
    cudaGetSymbolAddress((void**)&xr,   g_xr);
    cudaGetSymbolAddress((void**)&gat,  g_gat);
    cudaGetSymbolAddress((void**)&q,    g_q);
    cudaGetSymbolAddress((void**)&k,    g_k);
    cudaGetSymbolAddress((void**)&v,    g_v);
    cudaGetSymbolAddress((void**)&attn, g_attn);
    cudaGetSymbolAddress((void**)&fpart,g_fpart);
    cudaGetSymbolAddress((void**)&offs, g_offs);
    cudaGetSymbolAddress((void**)&elist,g_elist);

    // 1. CSR of base graph (same structure for all 32 graphs)
    build_csr<<<1, 256>>>(eidx, offs, elist);

    // 2a. Parallel RNN input projection: U[b] = xp[b] @ Wih^T + bih
    gemm_k<true,true><<<dim3(4, 4, 32), 256>>>(256, 256, 128,
        x, 256, 32768, Wih, 128, bih, u, 256, 65536);

    // 2b. Sequential recurrent scan: one-barrier full-tile steps
    const int rnn_smem = 2 * 256 * 34 * sizeof(float);   // 69632 B
    cudaFuncSetAttribute(rnn_step2,
        cudaFuncAttributeMaxDynamicSharedMemorySize, rnn_smem);
    for (int b = 0; b < 32; b++) {
        rnn_step2<<<64, 256, rnn_smem>>>(u + (size_t)b * 65536,
                                         b ? y + (size_t)(b - 1) * 65536 : nullptr,
                                         Whh, bhh,
                                         y + (size_t)b * 65536);
    }

    // 3. GAT linear transforms (merged): xl/xr = nodes @ Wl/Wr
    gemm128_z2<<<dim3(8, 64, 2), 256>>>(256, y, 256, Wl, Wr, 512, xl, xr, 512);

    // 4. GAT edge softmax + aggregation (writes gatout and alpha output)
    gat_node<<<8192, 256>>>(xl, xr, eidx, offs, elist, att, gbias,
                            gat, out + ALPHA_OFF);

    // 5. Q/K/V projections (merged) on Z = gatout reinterpreted [16384,256]
    gemm128_z3<<<dim3(4, 128, 3), 256>>>(256, gat, 256, Wq, Wk, Wv, 256,
                                         bq, bk, bv, q, k, v, 256);

    // 6. fused softmax(QK^T/8) @ V   (64 batches x 4 heads)
    attn_kernel<<<256, 256>>>(q, k, v, attn);

    // 7. recon = attn @ Wo + bo  -> d_out[0 : 4194304]
    gemm128_one<<<dim3(4, 128), 256>>>(256, attn, 256, Wo, 256, bo, out, 256);

    // 8. forecast = relu(z^T @ W1 + b1) @ W2 + b2 -> d_out[4194304 : +16384]
    gemm128_mlp<<<dim3(4, 128), 256>>>(gat, W1, b1, W2, fpart);
    forecast_reduce<<<64, 256>>>(fpart, b2, out + FORECAST_OFF);
}